// round 1
// baseline (speedup 1.0000x reference)
#include <cuda_runtime.h>
#include <math.h>

#define BATCH 32
#define SEQ   128
#define KDIM  1024
#define NCAPS 16
#define DCAPS 512
#define NDIM  (NCAPS * DCAPS)   // 8192
#define MDIM  (BATCH * SEQ)     // 4096
#define EPS   1e-7f

// Output layout: V (32*16*512), C_ret (3*32*128*16), B_logits (32*128*16)
#define OFF_V 0
#define OFF_C (BATCH * NCAPS * DCAPS)                  // 262144
#define OFF_B (OFF_C + 3 * BATCH * SEQ * NCAPS)        // 458752

// Scratch (device globals; no allocation allowed)
__device__ float g_U[(size_t)MDIM * NDIM];   // caps_uhat, 128 MiB
__device__ float g_B[BATCH * SEQ * NCAPS];   // routing logits (fully rewritten each run)

// ---------------------------------------------------------------------------
// GEMM (M=4096, K=1024, N=8192) + tanh epilogue -> g_U
// 128x128 tile, BK=16, 256 threads, 8x8 register tile
// ---------------------------------------------------------------------------
#define BM 128
#define BN 128
#define BK 16
#define TM 8
#define TN 8

__global__ __launch_bounds__(256) void gemm_tanh_kernel(
    const float* __restrict__ A, const float* __restrict__ W) {
  __shared__ float As[BK][BM];   // transposed A tile
  __shared__ float Bs[BK][BN];

  const int tid = threadIdx.x;
  const int rowBase = blockIdx.y * BM;
  const int colBase = blockIdx.x * BN;
  const int ty = tid >> 4;       // 0..15
  const int tx = tid & 15;       // 0..15

  float acc[TM][TN];
#pragma unroll
  for (int i = 0; i < TM; i++)
#pragma unroll
    for (int j = 0; j < TN; j++) acc[i][j] = 0.f;

  for (int kt = 0; kt < KDIM; kt += BK) {
    // Load A tile: 128 rows x 16 cols = 512 float4, 2 per thread
#pragma unroll
    for (int l = 0; l < 2; l++) {
      int i = tid + l * 256;
      int r = i >> 2, q = i & 3;
      float4 v = *(const float4*)&A[(size_t)(rowBase + r) * KDIM + kt + q * 4];
      As[q * 4 + 0][r] = v.x;
      As[q * 4 + 1][r] = v.y;
      As[q * 4 + 2][r] = v.z;
      As[q * 4 + 3][r] = v.w;
    }
    // Load W tile: 16 rows x 128 cols = 512 float4, 2 per thread
#pragma unroll
    for (int l = 0; l < 2; l++) {
      int i = tid + l * 256;
      int r = i >> 5, c4 = i & 31;
      *(float4*)&Bs[r][c4 * 4] =
          *(const float4*)&W[(size_t)(kt + r) * NDIM + colBase + c4 * 4];
    }
    __syncthreads();

#pragma unroll
    for (int k = 0; k < BK; k++) {
      float a[TM], b[TN];
      *(float4*)&a[0] = *(const float4*)&As[k][ty * TM];
      *(float4*)&a[4] = *(const float4*)&As[k][ty * TM + 4];
      *(float4*)&b[0] = *(const float4*)&Bs[k][tx * TN];
      *(float4*)&b[4] = *(const float4*)&Bs[k][tx * TN + 4];
#pragma unroll
      for (int i = 0; i < TM; i++)
#pragma unroll
        for (int j = 0; j < TN; j++) acc[i][j] = fmaf(a[i], b[j], acc[i][j]);
    }
    __syncthreads();
  }

  // tanh epilogue, vectorized store
#pragma unroll
  for (int i = 0; i < TM; i++) {
    float* dst = &g_U[(size_t)(rowBase + ty * TM + i) * NDIM + colBase + tx * TN];
    float4 o0, o1;
    o0.x = tanhf(acc[i][0]); o0.y = tanhf(acc[i][1]);
    o0.z = tanhf(acc[i][2]); o0.w = tanhf(acc[i][3]);
    o1.x = tanhf(acc[i][4]); o1.y = tanhf(acc[i][5]);
    o1.z = tanhf(acc[i][6]); o1.w = tanhf(acc[i][7]);
    *(float4*)dst = o0;
    *(float4*)(dst + 4) = o1;
  }
}

// ---------------------------------------------------------------------------
// Routing iteration: one CTA per (b, n). 256 threads.
//   - softmax over n (from g_B; uniform 1/16 at iter 0), write C_ret[iter]
//   - S[d] = sum_s C[s] * U[b,s,n,d]
//   - V = S / sqrt(||S||^2 + eps)  (write V if last iter)
//   - B[b,s,n] += <U[b,s,n,:], V>  (write B_logits if iter == 1)
// ---------------------------------------------------------------------------
__global__ __launch_bounds__(256) void routing_kernel(float* __restrict__ out,
                                                      int iter) {
  const int b = blockIdx.x >> 4;
  const int n = blockIdx.x & 15;
  const int tid = threadIdx.x;
  const int lane = tid & 31;
  const int warp = tid >> 5;

  __shared__ float Csh[SEQ];
  __shared__ float Vsh[DCAPS];
  __shared__ float wred[8];
  __shared__ float s_inv;

  // ---- softmax over capsules for each s (this CTA keeps column n) ----
  if (tid < SEQ) {
    float c;
    if (iter == 0) {
      c = 1.0f / NCAPS;
    } else {
      const float* brow = &g_B[(size_t)(b * SEQ + tid) * NCAPS];
      float mx = brow[0];
#pragma unroll
      for (int j = 1; j < NCAPS; j++) mx = fmaxf(mx, brow[j]);
      float sum = 0.f, mine = 0.f;
#pragma unroll
      for (int j = 0; j < NCAPS; j++) {
        float e = expf(brow[j] - mx);
        sum += e;
        if (j == n) mine = e;
      }
      c = mine / sum;
    }
    Csh[tid] = c;
    out[OFF_C + (size_t)((iter * BATCH + b) * SEQ + tid) * NCAPS + n] = c;
  }
  __syncthreads();

  // ---- S reduction over s; each thread owns d = tid and d = tid+256 ----
  const float* Ubn = &g_U[((size_t)(b * SEQ) * NCAPS + n) * DCAPS];
  float acc0 = 0.f, acc1 = 0.f;
#pragma unroll 4
  for (int s = 0; s < SEQ; s++) {
    float c = Csh[s];
    const float* u = Ubn + (size_t)s * NDIM;
    acc0 = fmaf(c, u[tid], acc0);
    acc1 = fmaf(c, u[tid + 256], acc1);
  }

  // ---- squash: block-reduce sum of squares ----
  float sq = acc0 * acc0 + acc1 * acc1;
#pragma unroll
  for (int o = 16; o > 0; o >>= 1) sq += __shfl_xor_sync(0xffffffffu, sq, o);
  if (lane == 0) wred[warp] = sq;
  __syncthreads();
  if (tid == 0) {
    float t = 0.f;
#pragma unroll
    for (int w = 0; w < 8; w++) t += wred[w];
    s_inv = 1.0f / sqrtf(t + EPS);
  }
  __syncthreads();
  const float inv = s_inv;
  const float v0 = acc0 * inv;
  const float v1 = acc1 * inv;
  Vsh[tid] = v0;
  Vsh[tid + 256] = v1;
  if (iter == 2) {
    float* vout = &out[OFF_V + (size_t)(b * NCAPS + n) * DCAPS];
    vout[tid] = v0;
    vout[tid + 256] = v1;
  }
  __syncthreads();

  // ---- agreement update: B[b,s,n] += <U[b,s,n,:], V> ----
  for (int s = warp; s < SEQ; s += 8) {
    const float* u = Ubn + (size_t)s * NDIM;
    float d = 0.f;
#pragma unroll
    for (int j = 0; j < DCAPS / 32; j++) {
      int dd = lane + j * 32;
      d = fmaf(u[dd], Vsh[dd], d);
    }
#pragma unroll
    for (int o = 16; o > 0; o >>= 1) d += __shfl_xor_sync(0xffffffffu, d, o);
    if (lane == 0) {
      int bi = (b * SEQ + s) * NCAPS + n;
      float nb = (iter == 0 ? 0.f : g_B[bi]) + d;
      g_B[bi] = nb;
      if (iter == 1) out[OFF_B + bi] = nb;  // B_logits = B entering last iter
    }
  }
}

// ---------------------------------------------------------------------------
extern "C" void kernel_launch(void* const* d_in, const int* in_sizes, int n_in,
                              void* d_out, int out_size) {
  const float* x = (const float*)d_in[0];   // (32,128,1024) f32
  const float* W = (const float*)d_in[1];   // (1024,8192) f32
  float* out = (float*)d_out;

  dim3 ggrid(NDIM / BN, MDIM / BM);  // (64, 32)
  gemm_tanh_kernel<<<ggrid, 256>>>(x, W);

  for (int it = 0; it < 3; it++)
    routing_kernel<<<BATCH * NCAPS, 256>>>(out, it);
}

// round 3
// speedup vs baseline: 2.0003x; 2.0003x over previous
#include <cuda_runtime.h>
#include <cuda_bf16.h>
#include <math.h>
#include <stdint.h>

#define BATCH 32
#define SEQ   128
#define KDIM  1024
#define NCAPS 16
#define DCAPS 512
#define NDIM  8192   // NCAPS*DCAPS
#define MDIM  4096   // BATCH*SEQ
#define EPS   1e-7f

// Output layout: V (32*16*512), C_ret (3*32*128*16), B_logits (32*128*16)
#define OFF_V 0
#define OFF_C (BATCH * NCAPS * DCAPS)              // 262144
#define OFF_B (OFF_C + 3 * BATCH * SEQ * NCAPS)    // 458752

// ---------------- device scratch (no allocation allowed) -------------------
__device__ float g_U[(size_t)MDIM * NDIM];            // caps_uhat (128 MiB)
__device__ float g_B[BATCH * SEQ * NCAPS];            // routing logits
__device__ __nv_bfloat16 g_Ahi[(size_t)MDIM * KDIM];  // x hi split [M,K]
__device__ __nv_bfloat16 g_Alo[(size_t)MDIM * KDIM];  // x lo split
__device__ __nv_bfloat16 g_Whi[(size_t)NDIM * KDIM];  // W^T hi split [N,K]
__device__ __nv_bfloat16 g_Wlo[(size_t)NDIM * KDIM];  // W^T lo split

// ---------------- PTX helpers (baseline ISA only — no 'a'-suffix features) --
__device__ __forceinline__ uint32_t smem_u32(const void* p) {
  uint32_t a;
  asm("{ .reg .u64 t; cvta.to.shared.u64 t, %1; cvt.u32.u64 %0, t; }"
      : "=r"(a) : "l"(p));
  return a;
}
__device__ __forceinline__ void cp16(uint32_t s, const void* g) {
  asm volatile("cp.async.cg.shared.global [%0], [%1], 16;" :: "r"(s), "l"(g));
}
#define CP_COMMIT() asm volatile("cp.async.commit_group;" ::: "memory")
#define CP_WAIT(n)  asm volatile("cp.async.wait_group %0;" :: "n"(n) : "memory")

#define LDSM_X4(r, a)                                                         \
  asm volatile("ldmatrix.sync.aligned.m8n8.x4.shared.b16 {%0,%1,%2,%3}, [%4];" \
      : "=r"((r)[0]), "=r"((r)[1]), "=r"((r)[2]), "=r"((r)[3]) : "r"(a))

#define MMA16816(d, a, b0, b1)                                                \
  asm volatile(                                                               \
      "mma.sync.aligned.m16n8k16.row.col.f32.bf16.bf16.f32 "                  \
      "{%0,%1,%2,%3}, {%4,%5,%6,%7}, {%8,%9}, {%0,%1,%2,%3};"                 \
      : "+f"((d)[0]), "+f"((d)[1]), "+f"((d)[2]), "+f"((d)[3])                \
      : "r"((a)[0]), "r"((a)[1]), "r"((a)[2]), "r"((a)[3]), "r"(b0), "r"(b1))

// ---------------- prep kernels ---------------------------------------------
__global__ __launch_bounds__(256) void split_a_kernel(const float* __restrict__ x) {
  size_t i = (size_t)blockIdx.x * 256 + threadIdx.x;  // float4 index
  float4 v = ((const float4*)x)[i];
  __nv_bfloat16 h0 = __float2bfloat16(v.x), h1 = __float2bfloat16(v.y);
  __nv_bfloat16 h2 = __float2bfloat16(v.z), h3 = __float2bfloat16(v.w);
  __nv_bfloat16 l0 = __float2bfloat16(v.x - __bfloat162float(h0));
  __nv_bfloat16 l1 = __float2bfloat16(v.y - __bfloat162float(h1));
  __nv_bfloat16 l2 = __float2bfloat16(v.z - __bfloat162float(h2));
  __nv_bfloat16 l3 = __float2bfloat16(v.w - __bfloat162float(h3));
  __nv_bfloat162 a, b;
  a.x = h0; a.y = h1; b.x = h2; b.y = h3;
  ((__nv_bfloat162*)g_Ahi)[2 * i] = a; ((__nv_bfloat162*)g_Ahi)[2 * i + 1] = b;
  a.x = l0; a.y = l1; b.x = l2; b.y = l3;
  ((__nv_bfloat162*)g_Alo)[2 * i] = a; ((__nv_bfloat162*)g_Alo)[2 * i + 1] = b;
}

// W [K, N] row-major -> W^T [N, K] bf16 hi/lo, tiled transpose
__global__ __launch_bounds__(256) void split_wt_kernel(const float* __restrict__ W) {
  __shared__ float tile[32][33];
  int n0 = blockIdx.x * 32, k0 = blockIdx.y * 32;
  int tx = threadIdx.x, ty = threadIdx.y;  // 32 x 8
#pragma unroll
  for (int j = 0; j < 4; j++)
    tile[ty + j * 8][tx] = W[(size_t)(k0 + ty + j * 8) * NDIM + n0 + tx];
  __syncthreads();
#pragma unroll
  for (int j = 0; j < 4; j++) {
    float v = tile[tx][ty + j * 8];  // = W[k0+tx][n0+ty+j*8]
    size_t o = (size_t)(n0 + ty + j * 8) * KDIM + k0 + tx;
    __nv_bfloat16 h = __float2bfloat16(v);
    g_Whi[o] = h;
    g_Wlo[o] = __float2bfloat16(v - __bfloat162float(h));
  }
}

// ---------------- HMMA GEMM + tanh -> g_U ----------------------------------
// CTA tile 128x128, BK=32, 256 threads (8 warps 2x4, warp tile 64x32).
// 3 bf16 passes per k-step: Ahi*Bhi + Ahi*Blo + Alo*Bhi.
#define ROWB 80                    // 64B data + 16B pad (conflict-free ldmatrix)
#define MAT_BYTES (128 * ROWB)     // 10240
#define STG_BYTES (4 * MAT_BYTES)  // Ahi, Alo, Bhi, Blo = 40960
#define NSTAGE 4
#define GEMM_SMEM (NSTAGE * STG_BYTES)  // 163840
#define NCHUNK (KDIM / 32)         // 32

__device__ __forceinline__ void load_stage(uint32_t s0, int rowBase, int colBase,
                                           int kt, int tid) {
#pragma unroll
  for (int l = 0; l < 2; l++) {
    int i = tid + l * 256;          // 0..511
    int r = i >> 2, c = i & 3;
    uint32_t off = (uint32_t)(r * ROWB + c * 16);
    size_t ga = (size_t)(rowBase + r) * KDIM + kt + c * 8;
    size_t gb = (size_t)(colBase + r) * KDIM + kt + c * 8;
    cp16(s0 + off, &g_Ahi[ga]);
    cp16(s0 + MAT_BYTES + off, &g_Alo[ga]);
    cp16(s0 + 2 * MAT_BYTES + off, &g_Whi[gb]);
    cp16(s0 + 3 * MAT_BYTES + off, &g_Wlo[gb]);
  }
}

__global__ __launch_bounds__(256, 1) void gemm_hmma_kernel() {
  extern __shared__ char smem[];
  const uint32_t sb = smem_u32(smem);
  const int tid = threadIdx.x;
  const int w = tid >> 5, lane = tid & 31;
  const int wr = w >> 2, wc = w & 3;          // warp row (0..1), col (0..3)
  const int rowBase = blockIdx.y * 128;
  const int colBase = blockIdx.x * 128;

  // per-lane ldmatrix offsets (within a stage)
  const int aRow = wr * 64 + (lane & 7) + ((lane >> 3) & 1) * 8;
  const uint32_t aOff = (uint32_t)(aRow * ROWB + ((lane >> 4) & 1) * 16);
  const int bRow = wc * 32 + (lane & 7) + ((lane >> 4) & 1) * 8;
  const uint32_t bOff = (uint32_t)(bRow * ROWB + ((lane >> 3) & 1) * 16);

  float acc[4][4][4];
#pragma unroll
  for (int i = 0; i < 4; i++)
#pragma unroll
    for (int j = 0; j < 4; j++)
#pragma unroll
      for (int q = 0; q < 4; q++) acc[i][j][q] = 0.f;

  // prefetch 3 stages
#pragma unroll
  for (int c = 0; c < 3; c++) {
    load_stage(sb + c * STG_BYTES, rowBase, colBase, c * 32, tid);
    CP_COMMIT();
  }

  for (int c = 0; c < NCHUNK; c++) {
    const uint32_t s0 = sb + (c & 3) * STG_BYTES;
    CP_WAIT(2);
    __syncthreads();
    // issue next load (buffer (c+3)&3 == (c-1)&3, free after the sync)
    if (c + 3 < NCHUNK) {
      load_stage(sb + ((c + 3) & 3) * STG_BYTES, rowBase, colBase, (c + 3) * 32, tid);
    }
    CP_COMMIT();

    const uint32_t sAh = s0 + aOff;
    const uint32_t sAl = s0 + MAT_BYTES + aOff;
    const uint32_t sBh = s0 + 2 * MAT_BYTES + bOff;
    const uint32_t sBl = s0 + 3 * MAT_BYTES + bOff;

#pragma unroll
    for (int s = 0; s < 2; s++) {          // two k16 steps in BK=32
      uint32_t ah[4][4], al[4][4], bh[2][4], bl[2][4];
#pragma unroll
      for (int i = 0; i < 4; i++) {
        LDSM_X4(ah[i], sAh + i * 16 * ROWB + s * 32);
        LDSM_X4(al[i], sAl + i * 16 * ROWB + s * 32);
      }
#pragma unroll
      for (int j = 0; j < 2; j++) {
        LDSM_X4(bh[j], sBh + j * 16 * ROWB + s * 32);
        LDSM_X4(bl[j], sBl + j * 16 * ROWB + s * 32);
      }
#pragma unroll
      for (int i = 0; i < 4; i++)
#pragma unroll
        for (int j = 0; j < 4; j++) {
          uint32_t b0h = bh[j >> 1][(j & 1) * 2], b1h = bh[j >> 1][(j & 1) * 2 + 1];
          uint32_t b0l = bl[j >> 1][(j & 1) * 2], b1l = bl[j >> 1][(j & 1) * 2 + 1];
          MMA16816(acc[i][j], ah[i], b0h, b1h);
          MMA16816(acc[i][j], ah[i], b0l, b1l);
          MMA16816(acc[i][j], al[i], b0h, b1h);
        }
    }
    __syncthreads();
  }

  // epilogue: tanh + store (thread owns rows lane/4 & +8, cols (lane%4)*2,+1)
  const int erow = rowBase + wr * 64 + (lane >> 2);
  const int ecol = colBase + wc * 32 + (lane & 3) * 2;
#pragma unroll
  for (int i = 0; i < 4; i++) {
#pragma unroll
    for (int j = 0; j < 4; j++) {
      float2 v0, v1;
      v0.x = tanhf(acc[i][j][0]); v0.y = tanhf(acc[i][j][1]);
      v1.x = tanhf(acc[i][j][2]); v1.y = tanhf(acc[i][j][3]);
      *(float2*)&g_U[(size_t)(erow + i * 16) * NDIM + ecol + j * 8] = v0;
      *(float2*)&g_U[(size_t)(erow + i * 16 + 8) * NDIM + ecol + j * 8] = v1;
    }
  }
}

// ---------------- routing iteration (512 threads / CTA) --------------------
__global__ __launch_bounds__(512) void routing_kernel(float* __restrict__ out,
                                                      int iter) {
  const int b = blockIdx.x >> 4;
  const int n = blockIdx.x & 15;
  const int tid = threadIdx.x;
  const int lane = tid & 31;
  const int warp = tid >> 5;

  __shared__ float Csh[SEQ];
  __shared__ float Vsh[DCAPS];
  __shared__ float wred[16];
  __shared__ float s_inv;

  if (tid < SEQ) {
    float c;
    if (iter == 0) {
      c = 1.0f / NCAPS;
    } else {
      const float* brow = &g_B[(size_t)(b * SEQ + tid) * NCAPS];
      float mx = brow[0];
#pragma unroll
      for (int j = 1; j < NCAPS; j++) mx = fmaxf(mx, brow[j]);
      float sum = 0.f, mine = 0.f;
#pragma unroll
      for (int j = 0; j < NCAPS; j++) {
        float e = expf(brow[j] - mx);
        sum += e;
        if (j == n) mine = e;
      }
      c = mine / sum;
    }
    Csh[tid] = c;
    out[OFF_C + (size_t)((iter * BATCH + b) * SEQ + tid) * NCAPS + n] = c;
  }
  __syncthreads();

  // S[d] = sum_s C[s] * U[b,s,n,d]; one thread per d
  const float* Ubn = &g_U[((size_t)(b * SEQ) * NCAPS + n) * DCAPS];
  float acc = 0.f;
#pragma unroll 4
  for (int s = 0; s < SEQ; s++)
    acc = fmaf(Csh[s], Ubn[(size_t)s * NDIM + tid], acc);

  float sq = acc * acc;
#pragma unroll
  for (int o = 16; o > 0; o >>= 1) sq += __shfl_xor_sync(0xffffffffu, sq, o);
  if (lane == 0) wred[warp] = sq;
  __syncthreads();
  if (tid == 0) {
    float t = 0.f;
#pragma unroll
    for (int k = 0; k < 16; k++) t += wred[k];
    s_inv = 1.0f / sqrtf(t + EPS);
  }
  __syncthreads();
  const float v = acc * s_inv;
  Vsh[tid] = v;
  if (iter == 2) out[OFF_V + (size_t)(b * NCAPS + n) * DCAPS + tid] = v;
  __syncthreads();

  // B[b,s,n] += <U[b,s,n,:], V>
  for (int s = warp; s < SEQ; s += 16) {
    const float* u = Ubn + (size_t)s * NDIM;
    float d = 0.f;
#pragma unroll
    for (int j = 0; j < DCAPS / 32; j++) {
      int dd = lane + j * 32;
      d = fmaf(u[dd], Vsh[dd], d);
    }
#pragma unroll
    for (int o = 16; o > 0; o >>= 1) d += __shfl_xor_sync(0xffffffffu, d, o);
    if (lane == 0) {
      int bi = (b * SEQ + s) * NCAPS + n;
      float nb = (iter == 0 ? 0.f : g_B[bi]) + d;
      g_B[bi] = nb;
      if (iter == 1) out[OFF_B + bi] = nb;
    }
  }
}

// ---------------------------------------------------------------------------
extern "C" void kernel_launch(void* const* d_in, const int* in_sizes, int n_in,
                              void* d_out, int out_size) {
  const float* x = (const float*)d_in[0];  // (32,128,1024) f32
  const float* W = (const float*)d_in[1];  // (1024,8192) f32
  float* out = (float*)d_out;

  cudaFuncSetAttribute(gemm_hmma_kernel,
                       cudaFuncAttributeMaxDynamicSharedMemorySize, GEMM_SMEM);

  split_a_kernel<<<MDIM * KDIM / (256 * 4), 256>>>(x);
  split_wt_kernel<<<dim3(NDIM / 32, KDIM / 32), dim3(32, 8)>>>(W);
  gemm_hmma_kernel<<<dim3(NDIM / 128, MDIM / 128), 256, GEMM_SMEM>>>();

  for (int it = 0; it < 3; it++)
    routing_kernel<<<BATCH * NCAPS, 512>>>(out, it);
}

// round 4
// speedup vs baseline: 2.2757x; 1.1377x over previous
#include <cuda_runtime.h>
#include <cuda_bf16.h>
#include <math.h>
#include <stdint.h>

#define BATCH 32
#define SEQ   128
#define KDIM  1024
#define NCAPS 16
#define DCAPS 512
#define NDIM  8192   // NCAPS*DCAPS
#define MDIM  4096   // BATCH*SEQ
#define EPS   1e-7f

// Output layout: V (32*16*512), C_ret (3*32*128*16), B_logits (32*128*16)
#define OFF_V 0
#define OFF_C (BATCH * NCAPS * DCAPS)              // 262144
#define OFF_B (OFF_C + 3 * BATCH * SEQ * NCAPS)    // 458752

// ---------------- device scratch (no allocation allowed) -------------------
__device__ float g_U[(size_t)MDIM * NDIM];            // caps_uhat (128 MiB)
__device__ float g_B[BATCH * SEQ * NCAPS];            // routing logits
__device__ float g_S[BATCH * NCAPS * DCAPS];          // S accumulator (zero steady-state)
__device__ float g_V[BATCH * NCAPS * DCAPS];          // V per iteration
__device__ __nv_bfloat16 g_Ahi[(size_t)MDIM * KDIM];  // x hi split [M,K]
__device__ __nv_bfloat16 g_Alo[(size_t)MDIM * KDIM];  // x lo split
__device__ __nv_bfloat16 g_Whi[(size_t)NDIM * KDIM];  // W^T hi split [N,K]
__device__ __nv_bfloat16 g_Wlo[(size_t)NDIM * KDIM];  // W^T lo split

// ---------------- PTX helpers (baseline ISA only) ---------------------------
__device__ __forceinline__ uint32_t smem_u32(const void* p) {
  uint32_t a;
  asm("{ .reg .u64 t; cvta.to.shared.u64 t, %1; cvt.u32.u64 %0, t; }"
      : "=r"(a) : "l"(p));
  return a;
}
__device__ __forceinline__ void cp16(uint32_t s, const void* g) {
  asm volatile("cp.async.cg.shared.global [%0], [%1], 16;" :: "r"(s), "l"(g));
}
#define CP_COMMIT() asm volatile("cp.async.commit_group;" ::: "memory")
#define CP_WAIT(n)  asm volatile("cp.async.wait_group %0;" :: "n"(n) : "memory")

#define LDSM_X4(r, a)                                                         \
  asm volatile("ldmatrix.sync.aligned.m8n8.x4.shared.b16 {%0,%1,%2,%3}, [%4];" \
      : "=r"((r)[0]), "=r"((r)[1]), "=r"((r)[2]), "=r"((r)[3]) : "r"(a))

#define MMA16816(d, a, b0, b1)                                                \
  asm volatile(                                                               \
      "mma.sync.aligned.m16n8k16.row.col.f32.bf16.bf16.f32 "                  \
      "{%0,%1,%2,%3}, {%4,%5,%6,%7}, {%8,%9}, {%0,%1,%2,%3};"                 \
      : "+f"((d)[0]), "+f"((d)[1]), "+f"((d)[2]), "+f"((d)[3])                \
      : "r"((a)[0]), "r"((a)[1]), "r"((a)[2]), "r"((a)[3]), "r"(b0), "r"(b1))

// ---------------- prep kernels ---------------------------------------------
__global__ __launch_bounds__(256) void split_a_kernel(const float* __restrict__ x) {
  size_t i = (size_t)blockIdx.x * 256 + threadIdx.x;  // float4 index
  float4 v = ((const float4*)x)[i];
  __nv_bfloat16 h0 = __float2bfloat16(v.x), h1 = __float2bfloat16(v.y);
  __nv_bfloat16 h2 = __float2bfloat16(v.z), h3 = __float2bfloat16(v.w);
  __nv_bfloat16 l0 = __float2bfloat16(v.x - __bfloat162float(h0));
  __nv_bfloat16 l1 = __float2bfloat16(v.y - __bfloat162float(h1));
  __nv_bfloat16 l2 = __float2bfloat16(v.z - __bfloat162float(h2));
  __nv_bfloat16 l3 = __float2bfloat16(v.w - __bfloat162float(h3));
  __nv_bfloat162 a, b;
  a.x = h0; a.y = h1; b.x = h2; b.y = h3;
  ((__nv_bfloat162*)g_Ahi)[2 * i] = a; ((__nv_bfloat162*)g_Ahi)[2 * i + 1] = b;
  a.x = l0; a.y = l1; b.x = l2; b.y = l3;
  ((__nv_bfloat162*)g_Alo)[2 * i] = a; ((__nv_bfloat162*)g_Alo)[2 * i + 1] = b;
}

// W [K, N] row-major -> W^T [N, K] bf16 hi/lo, tiled transpose
__global__ __launch_bounds__(256) void split_wt_kernel(const float* __restrict__ W) {
  __shared__ float tile[32][33];
  int n0 = blockIdx.x * 32, k0 = blockIdx.y * 32;
  int tx = threadIdx.x, ty = threadIdx.y;  // 32 x 8
#pragma unroll
  for (int j = 0; j < 4; j++)
    tile[ty + j * 8][tx] = W[(size_t)(k0 + ty + j * 8) * NDIM + n0 + tx];
  __syncthreads();
#pragma unroll
  for (int j = 0; j < 4; j++) {
    float v = tile[tx][ty + j * 8];
    size_t o = (size_t)(n0 + ty + j * 8) * KDIM + k0 + tx;
    __nv_bfloat16 h = __float2bfloat16(v);
    g_Whi[o] = h;
    g_Wlo[o] = __float2bfloat16(v - __bfloat162float(h));
  }
}

// ---------------- HMMA GEMM + tanh -> g_U ----------------------------------
// CTA tile 128x256, BK=32, 8 warps (2x4), warp tile 64x64, 3 smem stages.
#define ROWB 80
#define MAT_A 10240                // 128*80
#define MAT_B 20480                // 256*80
#define STG (2 * MAT_A + 2 * MAT_B)  // 61440
#define GEMM_SMEM (3 * STG)          // 184320
#define NCHUNK (KDIM / 32)           // 32

__device__ __forceinline__ void load_stage(uint32_t s0, int rowBase, int colBase,
                                           int kt, int tid) {
#pragma unroll
  for (int l = 0; l < 2; l++) {      // A hi+lo
    int i = tid + l * 256;           // 0..511
    int r = i >> 2, c = i & 3;
    uint32_t off = (uint32_t)(r * ROWB + c * 16);
    size_t ga = (size_t)(rowBase + r) * KDIM + kt + c * 8;
    cp16(s0 + off, &g_Ahi[ga]);
    cp16(s0 + MAT_A + off, &g_Alo[ga]);
  }
#pragma unroll
  for (int l = 0; l < 4; l++) {      // B hi+lo
    int i = tid + l * 256;           // 0..1023
    int r = i >> 2, c = i & 3;
    uint32_t off = (uint32_t)(r * ROWB + c * 16);
    size_t gb = (size_t)(colBase + r) * KDIM + kt + c * 8;
    cp16(s0 + 2 * MAT_A + off, &g_Whi[gb]);
    cp16(s0 + 2 * MAT_A + MAT_B + off, &g_Wlo[gb]);
  }
}

__global__ __launch_bounds__(256, 1) void gemm_hmma_kernel() {
  extern __shared__ char smem[];
  const uint32_t sb = smem_u32(smem);
  const int tid = threadIdx.x;
  const int w = tid >> 5, lane = tid & 31;
  const int wr = w >> 2, wc = w & 3;
  const int rowBase = blockIdx.y * 128;
  const int colBase = blockIdx.x * 256;

  const uint32_t aOff =
      (uint32_t)((wr * 64 + (lane & 7) + ((lane >> 3) & 1) * 8) * ROWB +
                 ((lane >> 4) & 1) * 16);
  const uint32_t bOff =
      (uint32_t)((wc * 64 + (lane & 7) + ((lane >> 4) & 1) * 8) * ROWB +
                 ((lane >> 3) & 1) * 16);

  float acc[4][8][4];
#pragma unroll
  for (int i = 0; i < 4; i++)
#pragma unroll
    for (int j = 0; j < 8; j++)
#pragma unroll
      for (int q = 0; q < 4; q++) acc[i][j][q] = 0.f;

  load_stage(sb, rowBase, colBase, 0, tid);
  CP_COMMIT();
  load_stage(sb + STG, rowBase, colBase, 32, tid);
  CP_COMMIT();

  int st = 0;
  for (int c = 0; c < NCHUNK; c++) {
    const uint32_t s0 = sb + st * STG;
    CP_WAIT(1);
    __syncthreads();
    if (c + 2 < NCHUNK) {
      int st2 = st + 2; if (st2 >= 3) st2 -= 3;
      load_stage(sb + st2 * STG, rowBase, colBase, (c + 2) * 32, tid);
    }
    CP_COMMIT();

#pragma unroll
    for (int s = 0; s < 2; s++) {
      uint32_t ah[4][4], al[4][4];
      const uint32_t sA = s0 + aOff + s * 32;
#pragma unroll
      for (int i = 0; i < 4; i++) {
        LDSM_X4(ah[i], sA + i * 16 * ROWB);
        LDSM_X4(al[i], sA + MAT_A + i * 16 * ROWB);
      }
      const uint32_t sB = s0 + 2 * MAT_A + bOff + s * 32;
#pragma unroll
      for (int jj = 0; jj < 4; jj++) {
        uint32_t bh[4], bl[4];
        LDSM_X4(bh, sB + jj * 16 * ROWB);
        LDSM_X4(bl, sB + MAT_B + jj * 16 * ROWB);
#pragma unroll
        for (int i = 0; i < 4; i++) {
          MMA16816(acc[i][jj * 2], ah[i], bh[0], bh[1]);
          MMA16816(acc[i][jj * 2], ah[i], bl[0], bl[1]);
          MMA16816(acc[i][jj * 2], al[i], bh[0], bh[1]);
          MMA16816(acc[i][jj * 2 + 1], ah[i], bh[2], bh[3]);
          MMA16816(acc[i][jj * 2 + 1], ah[i], bl[2], bl[3]);
          MMA16816(acc[i][jj * 2 + 1], al[i], bh[2], bh[3]);
        }
      }
    }
    st++; if (st == 3) st = 0;
  }

  // epilogue: tanh + store
  const int erow = rowBase + wr * 64 + (lane >> 2);
  const int ecol = colBase + wc * 64 + (lane & 3) * 2;
#pragma unroll
  for (int i = 0; i < 4; i++) {
#pragma unroll
    for (int j = 0; j < 8; j++) {
      float2 v0, v1;
      v0.x = tanhf(acc[i][j][0]); v0.y = tanhf(acc[i][j][1]);
      v1.x = tanhf(acc[i][j][2]); v1.y = tanhf(acc[i][j][3]);
      *(float2*)&g_U[(size_t)(erow + i * 16) * NDIM + ecol + j * 8] = v0;
      *(float2*)&g_U[(size_t)(erow + i * 16 + 8) * NDIM + ecol + j * 8] = v1;
    }
  }
}

// ---------------- fused routing pass: ONE read of U per iteration ----------
// CTA per (b, s-chunk of 8). Warp w owns capsule n=w. Per s:
//   dot = <U[b,s,n,:], V_prev[n,:]>  ->  B update  ->  row softmax -> C
//   S[n,:] += C * U[b,s,n,:]   (same registers)  -> atomicAdd partials.
__global__ __launch_bounds__(512) void pass_kernel(float* __restrict__ out,
                                                   int iter) {
  const int b = blockIdx.x >> 4;
  const int sc = blockIdx.x & 15;
  const int tid = threadIdx.x;
  const int lane = tid & 31;
  const int w = tid >> 5;  // capsule n

  __shared__ __align__(16) float Vsh[NCAPS * DCAPS];  // 32 KB
  __shared__ float dsh[8][NCAPS];
  __shared__ float csh[8][NCAPS];

  if (iter > 0) {
    const float4* vsrc = (const float4*)&g_V[(size_t)b * NCAPS * DCAPS];
    float4* vdst = (float4*)Vsh;
#pragma unroll
    for (int j = 0; j < 4; j++) vdst[tid + j * 512] = vsrc[tid + j * 512];
  }
  __syncthreads();

  const int s0 = sc * 8;
  const float* Ub = &g_U[((size_t)(b * SEQ + s0) * NCAPS + w) * DCAPS];
  float4 Sacc[4];
#pragma unroll
  for (int k = 0; k < 4; k++) Sacc[k] = make_float4(0.f, 0.f, 0.f, 0.f);

  for (int sb2 = 0; sb2 < 4; sb2++) {
    float4 Ur[2][4];
#pragma unroll
    for (int p = 0; p < 2; p++) {
      const float* row = Ub + (size_t)(sb2 * 2 + p) * NDIM;
#pragma unroll
      for (int k = 0; k < 4; k++)
        Ur[p][k] = *(const float4*)&row[128 * k + lane * 4];
    }
    if (iter > 0) {
#pragma unroll
      for (int p = 0; p < 2; p++) {
        float d = 0.f;
#pragma unroll
        for (int k = 0; k < 4; k++) {
          float4 vv = *(const float4*)&Vsh[w * DCAPS + 128 * k + lane * 4];
          d = fmaf(Ur[p][k].x, vv.x, d);
          d = fmaf(Ur[p][k].y, vv.y, d);
          d = fmaf(Ur[p][k].z, vv.z, d);
          d = fmaf(Ur[p][k].w, vv.w, d);
        }
#pragma unroll
        for (int o = 16; o > 0; o >>= 1) d += __shfl_xor_sync(0xffffffffu, d, o);
        if (lane == 0) dsh[sb2 * 2 + p][w] = d;
      }
    }
    __syncthreads();
    if (tid < 2) {
      const int sl = sb2 * 2 + tid;
      const int s = s0 + sl;
      const int bi0 = (b * SEQ + s) * NCAPS;
      if (iter == 0) {
#pragma unroll
        for (int n = 0; n < NCAPS; n++) {
          csh[sl][n] = 0.0625f;
          out[OFF_C + (size_t)(b * SEQ + s) * NCAPS + n] = 0.0625f;
        }
      } else {
        float Bv[NCAPS];
        float mx = -1e30f;
#pragma unroll
        for (int n = 0; n < NCAPS; n++) {
          float bo = (iter == 2) ? g_B[bi0 + n] : 0.f;
          Bv[n] = bo + dsh[sl][n];
          mx = fmaxf(mx, Bv[n]);
          if (iter == 1) g_B[bi0 + n] = Bv[n];
          else out[OFF_B + bi0 + n] = Bv[n];  // B_logits = B after iter-1 update
        }
        float sum = 0.f;
#pragma unroll
        for (int n = 0; n < NCAPS; n++) {
          Bv[n] = expf(Bv[n] - mx);
          sum += Bv[n];
        }
        float rs = 1.0f / sum;
#pragma unroll
        for (int n = 0; n < NCAPS; n++) {
          float c = Bv[n] * rs;
          csh[sl][n] = c;
          out[OFF_C + (size_t)((iter * BATCH + b) * SEQ + s) * NCAPS + n] = c;
        }
      }
    }
    __syncthreads();
#pragma unroll
    for (int p = 0; p < 2; p++) {
      float c = csh[sb2 * 2 + p][w];
#pragma unroll
      for (int k = 0; k < 4; k++) {
        Sacc[k].x = fmaf(c, Ur[p][k].x, Sacc[k].x);
        Sacc[k].y = fmaf(c, Ur[p][k].y, Sacc[k].y);
        Sacc[k].z = fmaf(c, Ur[p][k].z, Sacc[k].z);
        Sacc[k].w = fmaf(c, Ur[p][k].w, Sacc[k].w);
      }
    }
  }

  float* Sg = &g_S[(size_t)(b * NCAPS + w) * DCAPS];
#pragma unroll
  for (int k = 0; k < 4; k++) {
    int d0 = 128 * k + lane * 4;
    atomicAdd(&Sg[d0 + 0], Sacc[k].x);
    atomicAdd(&Sg[d0 + 1], Sacc[k].y);
    atomicAdd(&Sg[d0 + 2], Sacc[k].z);
    atomicAdd(&Sg[d0 + 3], Sacc[k].w);
  }
}

// squash: V = S / sqrt(||S||^2 + eps); re-zero S (keeps steady state zero)
__global__ __launch_bounds__(512) void squash_kernel(float* __restrict__ out,
                                                     int last) {
  const int bn = blockIdx.x;  // (b*16+n)
  const int tid = threadIdx.x;
  const int lane = tid & 31, warp = tid >> 5;
  __shared__ float wred[16];
  __shared__ float s_inv;

  size_t base = (size_t)bn * DCAPS;
  float s = g_S[base + tid];
  g_S[base + tid] = 0.f;
  float sq = s * s;
#pragma unroll
  for (int o = 16; o > 0; o >>= 1) sq += __shfl_xor_sync(0xffffffffu, sq, o);
  if (lane == 0) wred[warp] = sq;
  __syncthreads();
  if (tid == 0) {
    float t = 0.f;
#pragma unroll
    for (int k = 0; k < 16; k++) t += wred[k];
    s_inv = 1.0f / sqrtf(t + EPS);
  }
  __syncthreads();
  float v = s * s_inv;
  g_V[base + tid] = v;
  if (last) out[OFF_V + base + tid] = v;
}

// ---------------------------------------------------------------------------
extern "C" void kernel_launch(void* const* d_in, const int* in_sizes, int n_in,
                              void* d_out, int out_size) {
  const float* x = (const float*)d_in[0];  // (32,128,1024) f32
  const float* W = (const float*)d_in[1];  // (1024,8192) f32
  float* out = (float*)d_out;

  cudaFuncSetAttribute(gemm_hmma_kernel,
                       cudaFuncAttributeMaxDynamicSharedMemorySize, GEMM_SMEM);

  split_a_kernel<<<MDIM * KDIM / (256 * 4), 256>>>(x);
  split_wt_kernel<<<dim3(NDIM / 32, KDIM / 32), dim3(32, 8)>>>(W);
  gemm_hmma_kernel<<<dim3(NDIM / 256, MDIM / 128), 256, GEMM_SMEM>>>();

  for (int it = 0; it < 3; it++) {
    pass_kernel<<<BATCH * 16, 512>>>(out, it);
    squash_kernel<<<BATCH * NCAPS, 512>>>(out, it == 2);
  }
}

// round 5
// speedup vs baseline: 2.6411x; 1.1606x over previous
#include <cuda_runtime.h>
#include <cuda_bf16.h>
#include <cuda_fp16.h>
#include <math.h>
#include <stdint.h>

#define BATCH 32
#define SEQ   128
#define KDIM  1024
#define NCAPS 16
#define DCAPS 512
#define NDIM  8192   // NCAPS*DCAPS
#define MDIM  4096   // BATCH*SEQ
#define EPS   1e-7f

// Output layout: V (32*16*512), C_ret (3*32*128*16), B_logits (32*128*16)
#define OFF_V 0
#define OFF_C (BATCH * NCAPS * DCAPS)              // 262144
#define OFF_B (OFF_C + 3 * BATCH * SEQ * NCAPS)    // 458752

// ---------------- device scratch (no allocation allowed) -------------------
__device__ __half g_Uh[(size_t)MDIM * NDIM];          // caps_uhat fp16 (64 MiB)
__device__ float g_B[BATCH * SEQ * NCAPS];            // routing logits
__device__ float g_S[BATCH * NCAPS * DCAPS];          // S accumulator (zero steady-state)
__device__ float g_V[BATCH * NCAPS * DCAPS];          // V per iteration
__device__ __nv_bfloat16 g_Ahi[(size_t)MDIM * KDIM];  // x hi split [M,K]
__device__ __nv_bfloat16 g_Alo[(size_t)MDIM * KDIM];  // x lo split
__device__ __nv_bfloat16 g_Whi[(size_t)NDIM * KDIM];  // W^T hi split [N,K]
__device__ __nv_bfloat16 g_Wlo[(size_t)NDIM * KDIM];  // W^T lo split

// ---------------- PTX helpers (baseline ISA only) ---------------------------
__device__ __forceinline__ uint32_t smem_u32(const void* p) {
  uint32_t a;
  asm("{ .reg .u64 t; cvta.to.shared.u64 t, %1; cvt.u32.u64 %0, t; }"
      : "=r"(a) : "l"(p));
  return a;
}
__device__ __forceinline__ void cp16(uint32_t s, const void* g) {
  asm volatile("cp.async.cg.shared.global [%0], [%1], 16;" :: "r"(s), "l"(g));
}
#define CP_COMMIT() asm volatile("cp.async.commit_group;" ::: "memory")
#define CP_WAIT(n)  asm volatile("cp.async.wait_group %0;" :: "n"(n) : "memory")

#define LDSM_X4(r, a)                                                         \
  asm volatile("ldmatrix.sync.aligned.m8n8.x4.shared.b16 {%0,%1,%2,%3}, [%4];" \
      : "=r"((r)[0]), "=r"((r)[1]), "=r"((r)[2]), "=r"((r)[3]) : "r"(a))

#define MMA16816(d, a, b0, b1)                                                \
  asm volatile(                                                               \
      "mma.sync.aligned.m16n8k16.row.col.f32.bf16.bf16.f32 "                  \
      "{%0,%1,%2,%3}, {%4,%5,%6,%7}, {%8,%9}, {%0,%1,%2,%3};"                 \
      : "+f"((d)[0]), "+f"((d)[1]), "+f"((d)[2]), "+f"((d)[3])                \
      : "r"((a)[0]), "r"((a)[1]), "r"((a)[2]), "r"((a)[3]), "r"(b0), "r"(b1))

// ---------------- prep kernels ---------------------------------------------
__global__ __launch_bounds__(256) void split_a_kernel(const float* __restrict__ x) {
  size_t i = (size_t)blockIdx.x * 256 + threadIdx.x;  // float4 index
  float4 v = ((const float4*)x)[i];
  __nv_bfloat16 h0 = __float2bfloat16(v.x), h1 = __float2bfloat16(v.y);
  __nv_bfloat16 h2 = __float2bfloat16(v.z), h3 = __float2bfloat16(v.w);
  __nv_bfloat16 l0 = __float2bfloat16(v.x - __bfloat162float(h0));
  __nv_bfloat16 l1 = __float2bfloat16(v.y - __bfloat162float(h1));
  __nv_bfloat16 l2 = __float2bfloat16(v.z - __bfloat162float(h2));
  __nv_bfloat16 l3 = __float2bfloat16(v.w - __bfloat162float(h3));
  __nv_bfloat162 a, b;
  a.x = h0; a.y = h1; b.x = h2; b.y = h3;
  ((__nv_bfloat162*)g_Ahi)[2 * i] = a; ((__nv_bfloat162*)g_Ahi)[2 * i + 1] = b;
  a.x = l0; a.y = l1; b.x = l2; b.y = l3;
  ((__nv_bfloat162*)g_Alo)[2 * i] = a; ((__nv_bfloat162*)g_Alo)[2 * i + 1] = b;
}

// W [K, N] row-major -> W^T [N, K] bf16 hi/lo, tiled transpose
__global__ __launch_bounds__(256) void split_wt_kernel(const float* __restrict__ W) {
  __shared__ float tile[32][33];
  int n0 = blockIdx.x * 32, k0 = blockIdx.y * 32;
  int tx = threadIdx.x, ty = threadIdx.y;  // 32 x 8
#pragma unroll
  for (int j = 0; j < 4; j++)
    tile[ty + j * 8][tx] = W[(size_t)(k0 + ty + j * 8) * NDIM + n0 + tx];
  __syncthreads();
#pragma unroll
  for (int j = 0; j < 4; j++) {
    float v = tile[tx][ty + j * 8];
    size_t o = (size_t)(n0 + ty + j * 8) * KDIM + k0 + tx;
    __nv_bfloat16 h = __float2bfloat16(v);
    g_Whi[o] = h;
    g_Wlo[o] = __float2bfloat16(v - __bfloat162float(h));
  }
}

// ---------------- HMMA GEMM + tanh -> g_Uh (fp16) --------------------------
// CTA tile 128x128, BK=32, 8 warps (2x4), warp tile 64x32.
// XOR-swizzled smem (64B rows): off(r,c) = r*64 + (c ^ ((r>>1)&3))*16.
// 3 stages x 32KB = 96KB -> 2 CTAs/SM.
#define STG 32768
#define GEMM_SMEM (3 * STG)   // 98304
#define NCHUNK (KDIM / 32)    // 32

__device__ __forceinline__ void load_stage(uint32_t s0, int rowBase, int colBase,
                                           int kt, int tid) {
#pragma unroll
  for (int l = 0; l < 2; l++) {
    int i = tid + l * 256;           // 0..511
    int r = i >> 2, c = i & 3;
    uint32_t off = (uint32_t)(r * 64 + ((c ^ ((r >> 1) & 3)) << 4));
    size_t ga = (size_t)(rowBase + r) * KDIM + kt + c * 8;
    size_t gb = (size_t)(colBase + r) * KDIM + kt + c * 8;
    cp16(s0 + off, &g_Ahi[ga]);
    cp16(s0 + 8192 + off, &g_Alo[ga]);
    cp16(s0 + 16384 + off, &g_Whi[gb]);
    cp16(s0 + 24576 + off, &g_Wlo[gb]);
  }
}

__global__ __launch_bounds__(256, 2) void gemm_hmma_kernel() {
  extern __shared__ char smem[];
  const uint32_t sb = smem_u32(smem);
  const int tid = threadIdx.x;
  const int w = tid >> 5, lane = tid & 31;
  const int wr = w >> 2, wc = w & 3;          // warp row (0..1), col (0..3)
  const int rowBase = blockIdx.y * 128;
  const int colBase = blockIdx.x * 128;

  // per-lane fragment base addresses + swizzle keys
  const int selA = (lane >> 4) & 1;
  const int selB = (lane >> 3) & 1;
  uint32_t addrA[4], addrB[2];
  int xrA[4], xrB[2];
#pragma unroll
  for (int i = 0; i < 4; i++) {
    int r = wr * 64 + i * 16 + (lane & 7) + ((lane >> 3) & 1) * 8;
    addrA[i] = (uint32_t)(r * 64);
    xrA[i] = (r >> 1) & 3;
  }
#pragma unroll
  for (int jj = 0; jj < 2; jj++) {
    int r = wc * 32 + jj * 16 + (lane & 7) + ((lane >> 4) & 1) * 8;
    addrB[jj] = (uint32_t)(r * 64);
    xrB[jj] = (r >> 1) & 3;
  }

  float acc[4][4][4];
#pragma unroll
  for (int i = 0; i < 4; i++)
#pragma unroll
    for (int j = 0; j < 4; j++)
#pragma unroll
      for (int q = 0; q < 4; q++) acc[i][j][q] = 0.f;

  load_stage(sb, rowBase, colBase, 0, tid);
  CP_COMMIT();
  load_stage(sb + STG, rowBase, colBase, 32, tid);
  CP_COMMIT();

  int st = 0;
  for (int c = 0; c < NCHUNK; c++) {
    const uint32_t s0 = sb + st * STG;
    CP_WAIT(1);
    __syncthreads();
    if (c + 2 < NCHUNK) {
      int st2 = st + 2; if (st2 >= 3) st2 -= 3;
      load_stage(sb + st2 * STG, rowBase, colBase, (c + 2) * 32, tid);
    }
    CP_COMMIT();

#pragma unroll
    for (int s = 0; s < 2; s++) {
      const int ca = 2 * s + selA;
      const int cb = 2 * s + selB;
      uint32_t a[4][4], bh[2][4], bl[2][4];
#pragma unroll
      for (int i = 0; i < 4; i++)
        LDSM_X4(a[i], s0 + addrA[i] + ((uint32_t)(ca ^ xrA[i]) << 4));  // Ahi
#pragma unroll
      for (int jj = 0; jj < 2; jj++) {
        uint32_t boff = addrB[jj] + ((uint32_t)(cb ^ xrB[jj]) << 4);
        LDSM_X4(bh[jj], s0 + 16384 + boff);
        LDSM_X4(bl[jj], s0 + 24576 + boff);
      }
#pragma unroll
      for (int i = 0; i < 4; i++)
#pragma unroll
        for (int jj = 0; jj < 2; jj++) {
          MMA16816(acc[i][jj * 2],     a[i], bh[jj][0], bh[jj][1]);
          MMA16816(acc[i][jj * 2 + 1], a[i], bh[jj][2], bh[jj][3]);
          MMA16816(acc[i][jj * 2],     a[i], bl[jj][0], bl[jj][1]);
          MMA16816(acc[i][jj * 2 + 1], a[i], bl[jj][2], bl[jj][3]);
        }
#pragma unroll
      for (int i = 0; i < 4; i++)
        LDSM_X4(a[i], s0 + 8192 + addrA[i] + ((uint32_t)(ca ^ xrA[i]) << 4));  // Alo
#pragma unroll
      for (int i = 0; i < 4; i++)
#pragma unroll
        for (int jj = 0; jj < 2; jj++) {
          MMA16816(acc[i][jj * 2],     a[i], bh[jj][0], bh[jj][1]);
          MMA16816(acc[i][jj * 2 + 1], a[i], bh[jj][2], bh[jj][3]);
        }
    }
    st++; if (st == 3) st = 0;
  }

  // epilogue: tanh -> fp16 stores
  const int erow = rowBase + wr * 64 + (lane >> 2);
  const int ecol = colBase + wc * 32 + (lane & 3) * 2;
#pragma unroll
  for (int i = 0; i < 4; i++) {
#pragma unroll
    for (int j = 0; j < 4; j++) {
      __half2 v0 = __floats2half2_rn(tanhf(acc[i][j][0]), tanhf(acc[i][j][1]));
      __half2 v1 = __floats2half2_rn(tanhf(acc[i][j][2]), tanhf(acc[i][j][3]));
      *(__half2*)&g_Uh[(size_t)(erow + i * 16) * NDIM + ecol + j * 8] = v0;
      *(__half2*)&g_Uh[(size_t)(erow + i * 16 + 8) * NDIM + ecol + j * 8] = v1;
    }
  }
}

// ---------------- fused routing pass: ONE fp16 read of U per iteration -----
// CTA per (b, s-chunk of 8). Warp w owns capsule n=w; V_prev lives in registers.
__global__ __launch_bounds__(512) void pass_kernel(float* __restrict__ out,
                                                   int iter) {
  const int b = blockIdx.x >> 4;
  const int sc = blockIdx.x & 15;
  const int tid = threadIdx.x;
  const int lane = tid & 31;
  const int w = tid >> 5;  // capsule n

  __shared__ float dsh[8][NCAPS];
  __shared__ float csh[8][NCAPS];

  float Vreg[16];
  if (iter > 0) {
    const float* vp = &g_V[(size_t)(b * NCAPS + w) * DCAPS];
#pragma unroll
    for (int k = 0; k < 2; k++) {
      float4 u = *(const float4*)&vp[k * 256 + lane * 8];
      float4 v = *(const float4*)&vp[k * 256 + lane * 8 + 4];
      Vreg[k * 8 + 0] = u.x; Vreg[k * 8 + 1] = u.y;
      Vreg[k * 8 + 2] = u.z; Vreg[k * 8 + 3] = u.w;
      Vreg[k * 8 + 4] = v.x; Vreg[k * 8 + 5] = v.y;
      Vreg[k * 8 + 6] = v.z; Vreg[k * 8 + 7] = v.w;
    }
  }

  const int s0 = sc * 8;
  const __half* Ub = &g_Uh[((size_t)(b * SEQ + s0) * NCAPS + w) * DCAPS];
  float Sacc[16];
#pragma unroll
  for (int q = 0; q < 16; q++) Sacc[q] = 0.f;

  for (int g = 0; g < 4; g++) {
    float uf[2][16];
#pragma unroll
    for (int p = 0; p < 2; p++) {
      const uint4* up = (const uint4*)(Ub + (size_t)(g * 2 + p) * NDIM);
#pragma unroll
      for (int k = 0; k < 2; k++) {
        uint4 hv = up[lane + k * 32];
        float2 f0 = __half22float2(*(__half2*)&hv.x);
        float2 f1 = __half22float2(*(__half2*)&hv.y);
        float2 f2 = __half22float2(*(__half2*)&hv.z);
        float2 f3 = __half22float2(*(__half2*)&hv.w);
        uf[p][k * 8 + 0] = f0.x; uf[p][k * 8 + 1] = f0.y;
        uf[p][k * 8 + 2] = f1.x; uf[p][k * 8 + 3] = f1.y;
        uf[p][k * 8 + 4] = f2.x; uf[p][k * 8 + 5] = f2.y;
        uf[p][k * 8 + 6] = f3.x; uf[p][k * 8 + 7] = f3.y;
      }
    }
    if (iter > 0) {
#pragma unroll
      for (int p = 0; p < 2; p++) {
        float d = 0.f;
#pragma unroll
        for (int q = 0; q < 16; q++) d = fmaf(uf[p][q], Vreg[q], d);
#pragma unroll
        for (int o = 16; o > 0; o >>= 1) d += __shfl_xor_sync(0xffffffffu, d, o);
        if (lane == 0) dsh[g * 2 + p][w] = d;
      }
    }
    __syncthreads();
    if (tid < 2) {
      const int sl = g * 2 + tid;
      const int s = s0 + sl;
      const int bi0 = (b * SEQ + s) * NCAPS;
      if (iter == 0) {
#pragma unroll
        for (int n = 0; n < NCAPS; n++) {
          csh[sl][n] = 0.0625f;
          out[OFF_C + (size_t)(b * SEQ + s) * NCAPS + n] = 0.0625f;
        }
      } else {
        float Bv[NCAPS];
        float mx = -1e30f;
#pragma unroll
        for (int n = 0; n < NCAPS; n++) {
          float bo = (iter == 2) ? g_B[bi0 + n] : 0.f;
          Bv[n] = bo + dsh[sl][n];
          mx = fmaxf(mx, Bv[n]);
          if (iter == 1) g_B[bi0 + n] = Bv[n];
          else out[OFF_B + bi0 + n] = Bv[n];  // B_logits = B after iter-1 update
        }
        float sum = 0.f;
#pragma unroll
        for (int n = 0; n < NCAPS; n++) {
          Bv[n] = expf(Bv[n] - mx);
          sum += Bv[n];
        }
        float rs = 1.0f / sum;
#pragma unroll
        for (int n = 0; n < NCAPS; n++) {
          float cc = Bv[n] * rs;
          csh[sl][n] = cc;
          out[OFF_C + (size_t)((iter * BATCH + b) * SEQ + s) * NCAPS + n] = cc;
        }
      }
    }
    __syncthreads();
#pragma unroll
    for (int p = 0; p < 2; p++) {
      float cc = csh[g * 2 + p][w];
#pragma unroll
      for (int q = 0; q < 16; q++) Sacc[q] = fmaf(cc, uf[p][q], Sacc[q]);
    }
  }

  float* Sg = &g_S[(size_t)(b * NCAPS + w) * DCAPS];
#pragma unroll
  for (int k = 0; k < 2; k++)
#pragma unroll
    for (int j = 0; j < 8; j++)
      atomicAdd(&Sg[k * 256 + lane * 8 + j], Sacc[k * 8 + j]);
}

// squash: V = S / sqrt(||S||^2 + eps); re-zero S (keeps steady state zero)
__global__ __launch_bounds__(512) void squash_kernel(float* __restrict__ out,
                                                     int last) {
  const int bn = blockIdx.x;  // (b*16+n)
  const int tid = threadIdx.x;
  const int lane = tid & 31, warp = tid >> 5;
  __shared__ float wred[16];
  __shared__ float s_inv;

  size_t base = (size_t)bn * DCAPS;
  float s = g_S[base + tid];
  g_S[base + tid] = 0.f;
  float sq = s * s;
#pragma unroll
  for (int o = 16; o > 0; o >>= 1) sq += __shfl_xor_sync(0xffffffffu, sq, o);
  if (lane == 0) wred[warp] = sq;
  __syncthreads();
  if (tid == 0) {
    float t = 0.f;
#pragma unroll
    for (int k = 0; k < 16; k++) t += wred[k];
    s_inv = 1.0f / sqrtf(t + EPS);
  }
  __syncthreads();
  float v = s * s_inv;
  g_V[base + tid] = v;
  if (last) out[OFF_V + base + tid] = v;
}

// ---------------------------------------------------------------------------
extern "C" void kernel_launch(void* const* d_in, const int* in_sizes, int n_in,
                              void* d_out, int out_size) {
  const float* x = (const float*)d_in[0];  // (32,128,1024) f32
  const float* W = (const float*)d_in[1];  // (1024,8192) f32
  float* out = (float*)d_out;

  cudaFuncSetAttribute(gemm_hmma_kernel,
                       cudaFuncAttributeMaxDynamicSharedMemorySize, GEMM_SMEM);

  split_a_kernel<<<MDIM * KDIM / (256 * 4), 256>>>(x);
  split_wt_kernel<<<dim3(NDIM / 32, KDIM / 32), dim3(32, 8)>>>(W);
  gemm_hmma_kernel<<<dim3(NDIM / 128, MDIM / 128), 256, GEMM_SMEM>>>();

  for (int it = 0; it < 3; it++) {
    pass_kernel<<<BATCH * 16, 512>>>(out, it);
    squash_kernel<<<BATCH * NCAPS, 512>>>(out, it == 2);
  }
}

// round 8
// speedup vs baseline: 2.8666x; 1.0854x over previous
#include <cuda_runtime.h>
#include <cuda_bf16.h>
#include <cuda_fp16.h>
#include <math.h>
#include <stdint.h>

#define BATCH 32
#define SEQ   128
#define KDIM  1024
#define NCAPS 16
#define DCAPS 512
#define NDIM  8192   // NCAPS*DCAPS
#define MDIM  4096   // BATCH*SEQ
#define EPS   1e-7f

// Output layout: V (32*16*512), C_ret (3*32*128*16), B_logits (32*128*16)
#define OFF_V 0
#define OFF_C (BATCH * NCAPS * DCAPS)              // 262144
#define OFF_B (OFF_C + 3 * BATCH * SEQ * NCAPS)    // 458752

// ---------------- device scratch (no allocation allowed) -------------------
__device__ __half g_Uh[(size_t)MDIM * NDIM];          // caps_uhat fp16 (64 MiB)
__device__ float g_B[BATCH * SEQ * NCAPS];            // routing logits
__device__ float g_S[BATCH * NCAPS * DCAPS];          // S accumulator (zero steady-state)
__device__ float g_V[BATCH * NCAPS * DCAPS];          // V per iteration
__device__ __nv_bfloat16 g_Ahi[(size_t)MDIM * KDIM];  // x hi split [M,K]
__device__ __nv_bfloat16 g_Alo[(size_t)MDIM * KDIM];  // x lo split
__device__ __nv_bfloat16 g_Whi[(size_t)NDIM * KDIM];  // W^T hi split [N,K]
__device__ __nv_bfloat16 g_Wlo[(size_t)NDIM * KDIM];  // W^T lo split

// ---------------- PTX helpers (baseline ISA only) ---------------------------
__device__ __forceinline__ uint32_t smem_u32(const void* p) {
  uint32_t a;
  asm("{ .reg .u64 t; cvta.to.shared.u64 t, %1; cvt.u32.u64 %0, t; }"
      : "=r"(a) : "l"(p));
  return a;
}
__device__ __forceinline__ void cp16(uint32_t s, const void* g) {
  asm volatile("cp.async.cg.shared.global [%0], [%1], 16;" :: "r"(s), "l"(g));
}
#define CP_COMMIT() asm volatile("cp.async.commit_group;" ::: "memory")
#define CP_WAIT(n)  asm volatile("cp.async.wait_group %0;" :: "n"(n) : "memory")

#define LDSM_X4(r, a)                                                         \
  asm volatile("ldmatrix.sync.aligned.m8n8.x4.shared.b16 {%0,%1,%2,%3}, [%4];" \
      : "=r"((r)[0]), "=r"((r)[1]), "=r"((r)[2]), "=r"((r)[3]) : "r"(a))

#define MMA16816(d, a, b0, b1)                                                \
  asm volatile(                                                               \
      "mma.sync.aligned.m16n8k16.row.col.f32.bf16.bf16.f32 "                  \
      "{%0,%1,%2,%3}, {%4,%5,%6,%7}, {%8,%9}, {%0,%1,%2,%3};"                 \
      : "+f"((d)[0]), "+f"((d)[1]), "+f"((d)[2]), "+f"((d)[3])                \
      : "r"((a)[0]), "r"((a)[1]), "r"((a)[2]), "r"((a)[3]), "r"(b0), "r"(b1))

// fast tanh: Eigen-style odd rational, FMA-only + one MUFU.RCP; rel err ~1e-7
__device__ __forceinline__ float fast_tanh(float x) {
  float xc = fminf(fmaxf(x, -7.90531110763549805f), 7.90531110763549805f);
  float x2 = xc * xc;
  float p = -2.76076847742355e-16f;
  p = fmaf(p, x2, 2.00018790482477e-13f);
  p = fmaf(p, x2, -8.60467152213735e-11f);
  p = fmaf(p, x2, 5.12229709037114e-08f);
  p = fmaf(p, x2, 1.48572235717979e-05f);
  p = fmaf(p, x2, 6.37261928875436e-04f);
  p = fmaf(p, x2, 4.89352455891786e-03f);
  p = p * xc;
  float q = 1.19825839466702e-06f;
  q = fmaf(q, x2, 1.18534705686654e-04f);
  q = fmaf(q, x2, 2.26843463243900e-03f);
  q = fmaf(q, x2, 4.89352518554385e-03f);
  return __fdividef(p, q);
}

// ---------------- prep kernels ---------------------------------------------
__global__ __launch_bounds__(256) void split_a_kernel(const float* __restrict__ x) {
  size_t i = (size_t)blockIdx.x * 256 + threadIdx.x;  // float4 index
  float4 v = ((const float4*)x)[i];
  __nv_bfloat16 h0 = __float2bfloat16(v.x), h1 = __float2bfloat16(v.y);
  __nv_bfloat16 h2 = __float2bfloat16(v.z), h3 = __float2bfloat16(v.w);
  __nv_bfloat16 l0 = __float2bfloat16(v.x - __bfloat162float(h0));
  __nv_bfloat16 l1 = __float2bfloat16(v.y - __bfloat162float(h1));
  __nv_bfloat16 l2 = __float2bfloat16(v.z - __bfloat162float(h2));
  __nv_bfloat16 l3 = __float2bfloat16(v.w - __bfloat162float(h3));
  __nv_bfloat162 a, b;
  a.x = h0; a.y = h1; b.x = h2; b.y = h3;
  ((__nv_bfloat162*)g_Ahi)[2 * i] = a; ((__nv_bfloat162*)g_Ahi)[2 * i + 1] = b;
  a.x = l0; a.y = l1; b.x = l2; b.y = l3;
  ((__nv_bfloat162*)g_Alo)[2 * i] = a; ((__nv_bfloat162*)g_Alo)[2 * i + 1] = b;
}

// W [K, N] row-major -> W^T [N, K] bf16 hi/lo, tiled transpose
__global__ __launch_bounds__(256) void split_wt_kernel(const float* __restrict__ W) {
  __shared__ float tile[32][33];
  int n0 = blockIdx.x * 32, k0 = blockIdx.y * 32;
  int tx = threadIdx.x, ty = threadIdx.y;  // 32 x 8
#pragma unroll
  for (int j = 0; j < 4; j++)
    tile[ty + j * 8][tx] = W[(size_t)(k0 + ty + j * 8) * NDIM + n0 + tx];
  __syncthreads();
#pragma unroll
  for (int j = 0; j < 4; j++) {
    float v = tile[tx][ty + j * 8];
    size_t o = (size_t)(n0 + ty + j * 8) * KDIM + k0 + tx;
    __nv_bfloat16 h = __float2bfloat16(v);
    g_Whi[o] = h;
    g_Wlo[o] = __float2bfloat16(v - __bfloat162float(h));
  }
}

// ---------------- HMMA GEMM + tanh -> g_Uh (fp16) --------------------------
#define STG 32768
#define GEMM_SMEM (3 * STG)   // 98304
#define NCHUNK (KDIM / 32)    // 32

__device__ __forceinline__ void load_stage(uint32_t s0, int rowBase, int colBase,
                                           int kt, int tid) {
#pragma unroll
  for (int l = 0; l < 2; l++) {
    int i = tid + l * 256;           // 0..511
    int r = i >> 2, c = i & 3;
    uint32_t off = (uint32_t)(r * 64 + ((c ^ ((r >> 1) & 3)) << 4));
    size_t ga = (size_t)(rowBase + r) * KDIM + kt + c * 8;
    size_t gb = (size_t)(colBase + r) * KDIM + kt + c * 8;
    cp16(s0 + off, &g_Ahi[ga]);
    cp16(s0 + 8192 + off, &g_Alo[ga]);
    cp16(s0 + 16384 + off, &g_Whi[gb]);
    cp16(s0 + 24576 + off, &g_Wlo[gb]);
  }
}

__global__ __launch_bounds__(256, 2) void gemm_hmma_kernel() {
  extern __shared__ char smem[];
  const uint32_t sb = smem_u32(smem);
  const int tid = threadIdx.x;
  const int w = tid >> 5, lane = tid & 31;
  const int wr = w >> 2, wc = w & 3;
  const int rowBase = blockIdx.y * 128;
  const int colBase = blockIdx.x * 128;

  const int selA = (lane >> 4) & 1;
  const int selB = (lane >> 3) & 1;
  uint32_t addrA[4], addrB[2];
  int xrA[4], xrB[2];
#pragma unroll
  for (int i = 0; i < 4; i++) {
    int r = wr * 64 + i * 16 + (lane & 7) + ((lane >> 3) & 1) * 8;
    addrA[i] = (uint32_t)(r * 64);
    xrA[i] = (r >> 1) & 3;
  }
#pragma unroll
  for (int jj = 0; jj < 2; jj++) {
    int r = wc * 32 + jj * 16 + (lane & 7) + ((lane >> 4) & 1) * 8;
    addrB[jj] = (uint32_t)(r * 64);
    xrB[jj] = (r >> 1) & 3;
  }

  float acc[4][4][4];
#pragma unroll
  for (int i = 0; i < 4; i++)
#pragma unroll
    for (int j = 0; j < 4; j++)
#pragma unroll
      for (int q = 0; q < 4; q++) acc[i][j][q] = 0.f;

  load_stage(sb, rowBase, colBase, 0, tid);
  CP_COMMIT();
  load_stage(sb + STG, rowBase, colBase, 32, tid);
  CP_COMMIT();

  int st = 0;
  for (int c = 0; c < NCHUNK; c++) {
    const uint32_t s0 = sb + st * STG;
    CP_WAIT(1);
    __syncthreads();
    if (c + 2 < NCHUNK) {
      int st2 = st + 2; if (st2 >= 3) st2 -= 3;
      load_stage(sb + st2 * STG, rowBase, colBase, (c + 2) * 32, tid);
    }
    CP_COMMIT();

#pragma unroll
    for (int s = 0; s < 2; s++) {
      const int ca = 2 * s + selA;
      const int cb = 2 * s + selB;
      uint32_t a[4][4], bh[2][4], bl[2][4];
#pragma unroll
      for (int i = 0; i < 4; i++)
        LDSM_X4(a[i], s0 + addrA[i] + ((uint32_t)(ca ^ xrA[i]) << 4));  // Ahi
#pragma unroll
      for (int jj = 0; jj < 2; jj++) {
        uint32_t boff = addrB[jj] + ((uint32_t)(cb ^ xrB[jj]) << 4);
        LDSM_X4(bh[jj], s0 + 16384 + boff);
        LDSM_X4(bl[jj], s0 + 24576 + boff);
      }
#pragma unroll
      for (int i = 0; i < 4; i++)
#pragma unroll
        for (int jj = 0; jj < 2; jj++) {
          MMA16816(acc[i][jj * 2],     a[i], bh[jj][0], bh[jj][1]);
          MMA16816(acc[i][jj * 2 + 1], a[i], bh[jj][2], bh[jj][3]);
          MMA16816(acc[i][jj * 2],     a[i], bl[jj][0], bl[jj][1]);
          MMA16816(acc[i][jj * 2 + 1], a[i], bl[jj][2], bl[jj][3]);
        }
#pragma unroll
      for (int i = 0; i < 4; i++)
        LDSM_X4(a[i], s0 + 8192 + addrA[i] + ((uint32_t)(ca ^ xrA[i]) << 4));  // Alo
#pragma unroll
      for (int i = 0; i < 4; i++)
#pragma unroll
        for (int jj = 0; jj < 2; jj++) {
          MMA16816(acc[i][jj * 2],     a[i], bh[jj][0], bh[jj][1]);
          MMA16816(acc[i][jj * 2 + 1], a[i], bh[jj][2], bh[jj][3]);
        }
    }
    st++; if (st == 3) st = 0;
  }

  // epilogue: fast_tanh -> fp16 stores (1 MUFU per value)
  const int erow = rowBase + wr * 64 + (lane >> 2);
  const int ecol = colBase + wc * 32 + (lane & 3) * 2;
#pragma unroll
  for (int i = 0; i < 4; i++) {
#pragma unroll
    for (int j = 0; j < 4; j++) {
      __half2 v0 = __floats2half2_rn(fast_tanh(acc[i][j][0]), fast_tanh(acc[i][j][1]));
      __half2 v1 = __floats2half2_rn(fast_tanh(acc[i][j][2]), fast_tanh(acc[i][j][3]));
      *(__half2*)&g_Uh[(size_t)(erow + i * 16) * NDIM + ecol + j * 8] = v0;
      *(__half2*)&g_Uh[(size_t)(erow + i * 16 + 8) * NDIM + ecol + j * 8] = v1;
    }
  }
}

// ---------------- fused routing pass (warp-autonomous) ---------------------
// CTA per (b, s-chunk of 8), 256 threads (8 warps).
// Phase 1: warp w owns row s0+w; warp-local dots + softmax via shfl.
// Phase 2: warp w owns capsules n = w and n = w+8 (all 16 covered).
__global__ __launch_bounds__(256) void pass_kernel(float* __restrict__ out,
                                                   int iter) {
  const int b = blockIdx.x >> 4;
  const int sc = blockIdx.x & 15;
  const int tid = threadIdx.x;
  const int lane = tid & 31;
  const int w = tid >> 5;
  const int s0 = sc * 8;

  __shared__ __align__(16) float Vsh[NCAPS * DCAPS];  // 32 KB
  __shared__ float csh[8][NCAPS];

  if (iter > 0) {
    const float4* vsrc = (const float4*)&g_V[(size_t)b * NCAPS * DCAPS];
    float4* vdst = (float4*)Vsh;
#pragma unroll
    for (int j = 0; j < 8; j++) vdst[tid + j * 256] = vsrc[tid + j * 256];
    __syncthreads();
  }

  // ---- phase 1: warp w -> row s ----
  const int s = s0 + w;
  if (iter == 0) {
    if (lane < NCAPS) {
      csh[w][lane] = 0.0625f;
      out[OFF_C + (size_t)(b * SEQ + s) * NCAPS + lane] = 0.0625f;
    }
  } else {
    const __half* Us = &g_Uh[(size_t)(b * SEQ + s) * NDIM];
    float bv = 0.f;
#pragma unroll 4
    for (int n = 0; n < NCAPS; n++) {
      const uint2* up = (const uint2*)(Us + n * DCAPS);
      float d = 0.f;
#pragma unroll
      for (int j = 0; j < 4; j++) {
        uint2 hv = up[lane + j * 32];  // halves at d = lane*4 + j*128
        float2 f0 = __half22float2(*(__half2*)&hv.x);
        float2 f1 = __half22float2(*(__half2*)&hv.y);
        const float4 vv = *(const float4*)&Vsh[n * DCAPS + lane * 4 + j * 128];
        d = fmaf(f0.x, vv.x, d);
        d = fmaf(f0.y, vv.y, d);
        d = fmaf(f1.x, vv.z, d);
        d = fmaf(f1.y, vv.w, d);
      }
#pragma unroll
      for (int o = 16; o > 0; o >>= 1) d += __shfl_xor_sync(0xffffffffu, d, o);
      if (lane == n) bv = d;
    }
    const int bi0 = (b * SEQ + s) * NCAPS;
    float bfull = -1e30f;
    if (lane < NCAPS) {
      bfull = bv + (iter == 2 ? g_B[bi0 + lane] : 0.f);
      if (iter == 1) g_B[bi0 + lane] = bfull;
      else out[OFF_B + bi0 + lane] = bfull;  // B_logits = B entering last iter
    }
    float mx = bfull;
#pragma unroll
    for (int o = 8; o > 0; o >>= 1) mx = fmaxf(mx, __shfl_xor_sync(0xffffffffu, mx, o));
    float e = (lane < NCAPS) ? expf(bfull - mx) : 0.f;
    float sum = e;
#pragma unroll
    for (int o = 8; o > 0; o >>= 1) sum += __shfl_xor_sync(0xffffffffu, sum, o);
    if (lane < NCAPS) {
      float cc = e / sum;
      csh[w][lane] = cc;
      out[OFF_C + (size_t)((iter * BATCH + b) * SEQ + s) * NCAPS + lane] = cc;
    }
  }
  __syncthreads();

  // ---- phase 2: warp w -> capsules w and w+8 ----
#pragma unroll
  for (int half = 0; half < 2; half++) {
    const int n = w + half * 8;
    float Sacc[16];
#pragma unroll
    for (int q = 0; q < 16; q++) Sacc[q] = 0.f;
#pragma unroll
    for (int r = 0; r < 8; r++) {
      const float cc = csh[r][n];
      const uint2* up =
          (const uint2*)&g_Uh[((size_t)(b * SEQ + s0 + r) * NCAPS + n) * DCAPS];
#pragma unroll
      for (int j = 0; j < 4; j++) {
        uint2 hv = up[lane + j * 32];
        float2 f0 = __half22float2(*(__half2*)&hv.x);
        float2 f1 = __half22float2(*(__half2*)&hv.y);
        Sacc[j * 4 + 0] = fmaf(cc, f0.x, Sacc[j * 4 + 0]);
        Sacc[j * 4 + 1] = fmaf(cc, f0.y, Sacc[j * 4 + 1]);
        Sacc[j * 4 + 2] = fmaf(cc, f1.x, Sacc[j * 4 + 2]);
        Sacc[j * 4 + 3] = fmaf(cc, f1.y, Sacc[j * 4 + 3]);
      }
    }
    float* Sg = &g_S[(size_t)(b * NCAPS + n) * DCAPS];
#pragma unroll
    for (int j = 0; j < 4; j++)
#pragma unroll
      for (int q = 0; q < 4; q++)
        atomicAdd(&Sg[lane * 4 + j * 128 + q], Sacc[j * 4 + q]);
  }
}

// squash: V = S / sqrt(||S||^2 + eps); re-zero S (keeps steady state zero)
__global__ __launch_bounds__(512) void squash_kernel(float* __restrict__ out,
                                                     int last) {
  const int bn = blockIdx.x;  // (b*16+n)
  const int tid = threadIdx.x;
  const int lane = tid & 31, warp = tid >> 5;
  __shared__ float wred[16];
  __shared__ float s_inv;

  size_t base = (size_t)bn * DCAPS;
  float s = g_S[base + tid];
  g_S[base + tid] = 0.f;
  float sq = s * s;
#pragma unroll
  for (int o = 16; o > 0; o >>= 1) sq += __shfl_xor_sync(0xffffffffu, sq, o);
  if (lane == 0) wred[warp] = sq;
  __syncthreads();
  if (tid == 0) {
    float t = 0.f;
#pragma unroll
    for (int k = 0; k < 16; k++) t += wred[k];
    s_inv = 1.0f / sqrtf(t + EPS);
  }
  __syncthreads();
  float v = s * s_inv;
  g_V[base + tid] = v;
  if (last) out[OFF_V + base + tid] = v;
}

// ---------------------------------------------------------------------------
extern "C" void kernel_launch(void* const* d_in, const int* in_sizes, int n_in,
                              void* d_out, int out_size) {
  const float* x = (const float*)d_in[0];  // (32,128,1024) f32
  const float* W = (const float*)d_in[1];  // (1024,8192) f32
  float* out = (float*)d_out;

  cudaFuncSetAttribute(gemm_hmma_kernel,
                       cudaFuncAttributeMaxDynamicSharedMemorySize, GEMM_SMEM);

  split_a_kernel<<<MDIM * KDIM / (256 * 4), 256>>>(x);
  split_wt_kernel<<<dim3(NDIM / 32, KDIM / 32), dim3(32, 8)>>>(W);
  gemm_hmma_kernel<<<dim3(NDIM / 128, MDIM / 128), 256, GEMM_SMEM>>>();

  for (int it = 0; it < 3; it++) {
    pass_kernel<<<BATCH * 16, 256>>>(out, it);
    squash_kernel<<<BATCH * NCAPS, 512>>>(out, it == 2);
  }
}